// round 15
// baseline (speedup 1.0000x reference)
#include <cuda_runtime.h>
#include <math.h>

#define H   256
#define HD  64
#define NH  4
#define Bb  2
#define Qq  8
#define Tt  512
#define L   16           // chunk length (timesteps)
#define NC  32           // Tt / L
#define EB  16
#define BT  1024
#define NEGc (-0.6065306597126334f)
#define EPSc 0.00064f

// ---------------- scratch (device globals; no allocations) ----------------
__device__ float g_K  [BT*H];
__device__ float g_Vb [BT*H];
__device__ float g_sigv[BT*H];
__device__ float g_hA [BT*H];
__device__ float g_Hw1[BT*32];
__device__ float g_qw1[EB*32];
__device__ float g_qA [EB*H];
__device__ float g_rlast[EB*H];
__device__ float g_glast[EB*H];
__device__ float g_o  [EB*H];
__device__ int   g_cnt[EB];
// chunked scan inputs
__device__ float  g_W [(size_t)EB*NC*L*H];   // Ŵ_i = P_i ∘ kf
__device__ float  g_Bv[(size_t)EB*NC*L*H];   // B̂_i = P_i ∘ bv
__device__ float2 g_NV[(size_t)EB*NC*L*H];   // {ñ_m, vv}
__device__ float  g_Ep[(size_t)EB*NC*H];     // Ê = P_L
__device__ float2 g_Q2[(size_t)EB*NC*NH*L*L]; // {QK, QB}

__device__ __forceinline__ float sigmoidf_(float x) { return 1.f / (1.f + __expf(-x)); }

__device__ __forceinline__ float wsum(float v) {
    #pragma unroll
    for (int o = 16; o; o >>= 1) v += __shfl_xor_sync(0xffffffffu, v, o);
    return v;
}

// ---------------- k1: merged per-bt chains + per-eb chains + K/V GEMM ----------------
__global__ void __launch_bounds__(256) k_prep(
        const float* __restrict__ keyval, const float* __restrict__ query,
        const float* __restrict__ x_k, const float* __restrict__ x_v,
        const float* __restrict__ x_w, const float* __restrict__ x_a,
        const float* __restrict__ x_r, const float* __restrict__ x_g,
        const float* __restrict__ w1, const float* __restrict__ v1,
        const float* __restrict__ a1, const float* __restrict__ v2,
        const float* __restrict__ a2, const float* __restrict__ v0,
        const float* __restrict__ g1, const float* __restrict__ g2,
        const float* __restrict__ Wr, const float* __restrict__ Wk,
        const float* __restrict__ Wv) {
    int blk = blockIdx.x;
    int j = threadIdx.x;
    __shared__ float s0[H], s1[H], s2[H], s3[H];
    __shared__ float red[4][8][32];
    __shared__ float mid[4][32];
    __shared__ float As[64][33];
    __shared__ float Ws[64][33];
    if (blk < BT) {
        // ---- per-(b,t) small chains ----
        int w = j >> 5, ln = j & 31;
        int bt = blk, t = bt & (Tt - 1);
        float hs = keyval[bt*H + j];
        float hp = (t > 0) ? keyval[(bt-1)*H + j] : 0.f;
        s0[j] = fmaf(hp - hs, x_v[j], hs);   // xv
        s1[j] = hs * (1.f - x_w[j]);         // xwh
        s2[j] = hs * (1.f - x_a[j]);         // xah
        __syncthreads();
        int kbase = w * 32;
        float pw = 0.f, pv = 0.f, pa = 0.f;
        #pragma unroll
        for (int kk = 0; kk < 32; kk++) {
            int k = kbase + kk;
            pw = fmaf(s1[k], w1[k*32 + ln], pw);
            pv = fmaf(s0[k], v1[k*32 + ln], pv);
            pa = fmaf(s2[k], a1[k*32 + ln], pa);
        }
        red[0][w][ln] = pw; red[1][w][ln] = pv; red[2][w][ln] = pa;
        __syncthreads();
        if (j < 96) {
            int m = j >> 5, d = j & 31;
            float s = 0.f;
            #pragma unroll
            for (int ww = 0; ww < 8; ww++) s += red[m][ww][d];
            mid[m][d] = s;
            if (m == 0) g_Hw1[bt*32 + d] = s;
        }
        __syncthreads();
        float av = 0.f, aa = 0.f;
        #pragma unroll
        for (int d = 0; d < 32; d++) {
            av = fmaf(mid[1][d], v2[d*H + j], av);
            aa = fmaf(mid[2][d], a2[d*H + j], aa);
        }
        g_sigv[bt*H + j] = sigmoidf_(av + v0[j]);
        g_hA[bt*H + j]   = aa;
    } else if (blk < BT + EB) {
        // ---- per-eb small chains ----
        int w = j >> 5, ln = j & 31;
        int eb = blk - BT; int b = eb >> 3;
        if (j == 0) g_cnt[eb] = 0;            // reset ticket each launch
        float qv  = query[eb*H + j];
        float hsL = keyval[(b*Tt + Tt - 1)*H + j];
        s0[j] = fmaf(qv - hsL, x_r[j], hsL);  // xr
        s1[j] = fmaf(qv - hsL, x_g[j], hsL);  // xg
        s2[j] = qv * x_w[j];                  // xw (query part)
        s3[j] = qv * x_a[j];                  // xa (query part)
        __syncthreads();
        int kbase = w * 32;
        float pw = 0.f, pa = 0.f, pg0 = 0.f, pg1 = 0.f;
        #pragma unroll
        for (int kk = 0; kk < 32; kk++) {
            int k = kbase + kk;
            pw  = fmaf(s2[k], w1[k*32 + ln], pw);
            pa  = fmaf(s3[k], a1[k*32 + ln], pa);
            pg0 = fmaf(s1[k], g1[k*64 + ln], pg0);
            pg1 = fmaf(s1[k], g1[k*64 + 32 + ln], pg1);
        }
        red[0][w][ln] = pw; red[1][w][ln] = pa; red[2][w][ln] = pg0; red[3][w][ln] = pg1;
        __syncthreads();
        if (j < 128) {
            int m = j >> 5, d = j & 31;
            float s = 0.f;
            #pragma unroll
            for (int ww = 0; ww < 8; ww++) s += red[m][ww][d];
            if      (m == 0) g_qw1[eb*32 + d] = s;
            else if (m == 1) mid[1][d] = s;               // ta
            else if (m == 2) mid[2][d] = sigmoidf_(s);    // tg[0:32]
            else             mid[3][d] = sigmoidf_(s);    // tg[32:64]
        }
        __syncthreads();
        float aa = 0.f, gg = 0.f;
        #pragma unroll
        for (int d = 0; d < 32; d++) {
            aa = fmaf(mid[1][d], a2[d*H + j], aa);
            gg = fmaf(mid[2][d], g2[d*H + j], gg);
        }
        #pragma unroll
        for (int d = 0; d < 32; d++) gg = fmaf(mid[3][d], g2[(32 + d)*H + j], gg);
        g_qA[eb*H + j]    = aa;
        g_glast[eb*H + j] = gg;
        float acc = 0.f;
        const float4* __restrict__ Wrow = (const float4*)(Wr + j*H);
        #pragma unroll 16
        for (int k4 = 0; k4 < 64; k4++) {
            float4 wv = Wrow[k4];
            acc += s0[4*k4]*wv.x + s0[4*k4+1]*wv.y + s0[4*k4+2]*wv.z + s0[4*k4+3]*wv.w;
        }
        g_rlast[eb*H + j] = acc;
    } else {
        // ---- K / Vb GEMM tile ----
        int gb = blk - (BT + EB);         // 0..127
        int bmI = gb & 15, bnI = (gb >> 4) & 3, z = gb >> 6;
        const float* __restrict__ xm = z ? x_v : x_k;
        const float* __restrict__ W  = z ? Wv  : Wk;
        float* __restrict__ C = z ? g_Vb : g_K;
        int tid = j;
        int tx = tid & 15, ty = tid >> 4;
        int bm = bmI * 64, bn = bnI * 64;
        float acc[4][4] = {};
        #pragma unroll 1
        for (int k0 = 0; k0 < H; k0 += 32) {
            #pragma unroll
            for (int l = tid; l < 64*32; l += 256) {
                int r = l >> 5, c = l & 31;
                int m = bm + r, kg = k0 + c;
                int t = m & (Tt - 1);
                float hs = keyval[m*H + kg];
                float hp = (t > 0) ? keyval[(m-1)*H + kg] : 0.f;
                As[r][c] = fmaf(hp - hs, __ldg(&xm[kg]), hs);
                Ws[r][c] = W[(bn + r)*H + kg];
            }
            __syncthreads();
            #pragma unroll
            for (int kk = 0; kk < 32; kk++) {
                float a_[4], w_[4];
                #pragma unroll
                for (int i = 0; i < 4; i++) { a_[i] = As[ty + 16*i][kk]; w_[i] = Ws[tx + 16*i][kk]; }
                #pragma unroll
                for (int i = 0; i < 4; i++)
                    #pragma unroll
                    for (int jj = 0; jj < 4; jj++) acc[i][jj] = fmaf(a_[i], w_[jj], acc[i][jj]);
            }
            __syncthreads();
        }
        #pragma unroll
        for (int i = 0; i < 4; i++)
            #pragma unroll
            for (int jj = 0; jj < 4; jj++)
                C[(bm + ty + 16*i)*H + (bn + tx + 16*jj)] = acc[i][jj];
    }
}

// ---------------- k2: per-(eb, chunk) precompute ----------------
__global__ void __launch_bounds__(256) k_chunk(
        const float* __restrict__ v_first, const float* __restrict__ w2,
        const float* __restrict__ w0, const float* __restrict__ a0,
        const float* __restrict__ k_a, const float* __restrict__ k_k) {
    int p = blockIdx.x, eb = blockIdx.y;
    int b = eb >> 3;
    int j = threadIdx.x;             // 256
    int w = j >> 5, ln = j & 31;
    __shared__ float th[L][32];
    __shared__ float sN[L][H+1];
    __shared__ float sW[L][H+1];
    __shared__ float nb[8];
    for (int idx = j; idx < L*32; idx += 256) {
        int i = idx >> 5, d = idx & 31;
        int t = p*L + (L-1) - i;
        th[i][d] = tanhf(g_Hw1[(b*Tt + t)*32 + d] + g_qw1[eb*32 + d]);
    }
    __syncthreads();
    float w0j = w0[j], a0j = a0[j], kaj = k_a[j], kkj = k_k[j], qAj = g_qA[eb*H + j];
    float w2c[32];
    #pragma unroll
    for (int d = 0; d < 32; d++) w2c[d] = w2[d*H + j];
    float P = 1.f;
    #pragma unroll 1
    for (int i = 0; i < L; i++) {
        int t = p*L + (L-1) - i;
        int bt = b*Tt + t;
        float ac = 0.f;
        #pragma unroll
        for (int d = 0; d < 32; d++) ac = fmaf(th[i][d], w2c[d], ac);
        float ew = __expf(NEGc * sigmoidf_(w0j + ac));
        float Kv = g_K[bt*H + j];
        float kkv = Kv * kkj;
        float sqp = wsum(kkv * kkv);
        if (ln == 0) nb[w] = sqp;
        __syncthreads();
        int head = j >> 6;
        float nrm = sqrtf(nb[2*head] + nb[2*head + 1]);
        float kk = kkv / fmaxf(nrm, 1e-12f);
        __syncthreads();
        float a4 = sigmoidf_(a0j + g_hA[bt*H + j] + qAj);
        float kf = Kv * fmaf(a4 - 1.f, kaj, 1.f);
        float bvv = kk * a4;
        float vb = g_Vb[bt*H + j], sv = g_sigv[bt*H + j];
        float vv = fmaf(v_first[((size_t)eb*Tt + t)*H + j] - vb, sv, vb);
        float Wi = P * kf;
        float Bi = P * bvv;
        float Ni = kk / (P * ew);
        sN[i][j] = Ni; sW[i][j] = Wi;
        size_t o = (((size_t)eb*NC + p)*L + i)*H + j;
        g_W[o] = Wi; g_Bv[o] = Bi;
        g_NV[o] = make_float2(Ni, vv);
        P *= ew;
    }
    g_Ep[((size_t)eb*NC + p)*H + j] = P;
    __syncthreads();
    size_t qbase = (((size_t)eb*NC + p)*NH) * (L*L);
    for (int idx = j; idx < NH*120; idx += 256) {
        int hh = idx / 120;
        int r = idx % 120;
        int i = (int)((1.0f + sqrtf(1.0f + 8.0f*(float)r)) * 0.5f);
        int tri = (i*(i-1)) >> 1;
        if (r < tri) { i--; tri = (i*(i-1)) >> 1; }
        else if (r >= tri + i) { i++; tri = (i*(i-1)) >> 1; }
        int m = r - tri;
        int base = hh * 64;
        float acc = 0.f;
        #pragma unroll
        for (int d = 0; d < 64; d++) acc = fmaf(sN[m][base+d], sW[i][base+d], acc);
        g_Q2[qbase + (size_t)hh*(L*L) + m*L + i].x = acc;
    }
    __syncthreads();
    for (int idx = j; idx < L*H; idx += 256) {
        int i = idx >> 8, d = idx & 255;
        sW[i][d] = g_Bv[(((size_t)eb*NC + p)*L + i)*H + d];
    }
    __syncthreads();
    for (int idx = j; idx < NH*120; idx += 256) {
        int hh = idx / 120;
        int r = idx % 120;
        int i = (int)((1.0f + sqrtf(1.0f + 8.0f*(float)r)) * 0.5f);
        int tri = (i*(i-1)) >> 1;
        if (r < tri) { i--; tri = (i*(i-1)) >> 1; }
        else if (r >= tri + i) { i++; tri = (i*(i-1)) >> 1; }
        int m = r - tri;
        int base = hh * 64;
        float acc = 0.f;
        #pragma unroll
        for (int d = 0; d < 64; d++) acc = fmaf(sN[m][base+d], sW[i][base+d], acc);
        g_Q2[qbase + (size_t)hh*(L*L) + m*L + i].y = acc;
    }
}

// ---------------- k3: chunked backward scan (3 syncs/round) + fused Wo GEMV ----------------
__global__ void __launch_bounds__(256) k_scan(const float* __restrict__ r_k,
                        const float* __restrict__ gn_w, const float* __restrict__ gn_b,
                        const float* __restrict__ Wo, float* __restrict__ out) {
    int blk = blockIdx.x;
    int eb = blk >> 2, h = blk & 3;
    int tid = threadIdx.x;
    int jb = h * 64;
    __shared__ float su[64], so[64];
    __shared__ float rs[L], es[L], cs[L], ss[L];
    __shared__ float osbuf[4][64];        // reused as os in fused tail
    __shared__ float r1s[64], r2s[64], r3s[64];
    __shared__ float fin[3];
    __shared__ int sOld;
    if (tid < 64) { su[tid] = g_rlast[eb*H + jb + tid]; so[tid] = 0.f; }
    __syncthreads();
    int i16 = tid >> 4;   // reduction-vector index 0..15
    int jg  = tid & 15;   // dim group (4 dims each)
    // prefetch phase-1 vectors for chunk NC-1
    float4 wv, bvv;
    {
        size_t cb0 = ((size_t)eb*NC + (NC-1))*L*H + jb;
        wv  = *((const float4*)(g_W  + cb0 + (size_t)i16*H) + jg);
        bvv = *((const float4*)(g_Bv + cb0 + (size_t)i16*H) + jg);
    }
    #pragma unroll 1
    for (int p = NC - 1; p >= 0; --p) {
        size_t cb = ((size_t)eb*NC + p)*L*H + jb;
        // round-start loads: NV (tid<64, 16 each), Ep (tid<64), Q2 (tid<16)
        float2 nv[16];
        float Ereg = 0.f;
        if (tid < 64) {
            #pragma unroll
            for (int m = 0; m < L; m++) nv[m] = g_NV[cb + (size_t)m*H + tid];
            Ereg = g_Ep[((size_t)eb*NC + p)*H + jb + tid];
        }
        float2 qcol[L];
        if (tid < 16) {
            size_t qb = (((size_t)eb*NC + p)*NH + h)*(L*L);
            #pragma unroll
            for (int m = 0; m < L; m++) qcol[m] = g_Q2[qb + m*L + tid];
        }
        // phase 1: raw dots r_i = u·Ŵ_i, e_i = u·B̂_i
        float u0 = su[jg*4], u1 = su[jg*4+1], u2 = su[jg*4+2], u3 = su[jg*4+3];
        float pr = u0*wv.x + u1*wv.y + u2*wv.z + u3*wv.w;
        float pe = u0*bvv.x + u1*bvv.y + u2*bvv.z + u3*bvv.w;
        if (p > 0) {
            size_t cbn = ((size_t)eb*NC + (p-1))*L*H + jb;
            wv  = *((const float4*)(g_W  + cbn + (size_t)i16*H) + jg);
            bvv = *((const float4*)(g_Bv + cbn + (size_t)i16*H) + jg);
        }
        #pragma unroll
        for (int off = 8; off; off >>= 1) {
            pr += __shfl_xor_sync(0xffffffffu, pr, off);
            pe += __shfl_xor_sync(0xffffffffu, pe, off);
        }
        if (jg == 0) { rs[i16] = pr; es[i16] = pe; }
        __syncthreads();
        // phase 2: triangular solve (lanes 0..15 of warp 0)
        if (tid < 16) {
            float c = rs[tid], s = es[tid];
            #pragma unroll
            for (int m = 0; m < L-1; m++) {
                float sm = __shfl_sync(0x0000ffffu, s, m, 16);
                if (tid > m) {
                    c = fmaf(-sm, qcol[m].x, c);
                    s = fmaf(-sm, qcol[m].y, s);
                }
            }
            cs[tid] = c; ss[tid] = s;
        }
        __syncthreads();
        // phase 3: direct o/u update (tid<64)
        if (tid < 64) {
            float accO = 0.f, accU = 0.f;
            #pragma unroll
            for (int m = 0; m < L; m++) {
                accO = fmaf(cs[m], nv[m].y, accO);
                accU = fmaf(ss[m], nv[m].x, accU);
            }
            so[tid] += accO;
            su[tid] = Ereg * (su[tid] - accU);
        }
        __syncthreads();
    }
    // epilogue: groupnorm + residual + gate
    if (tid < 64) {
        float o = so[tid];
        r1s[tid] = o;
        r2s[tid] = o*o;
        size_t lw = (((size_t)eb*NC + (NC-1))*L + 0)*H + jb + tid;  // Ŵ (=kf) at t=T-1
        r3s[tid] = g_rlast[eb*H + jb + tid] * g_W[lw] * r_k[jb + tid];
    }
    __syncthreads();
    if (tid < 32) {
        r1s[tid] += r1s[tid + 32];
        r2s[tid] += r2s[tid + 32];
        r3s[tid] += r3s[tid + 32];
        float a = wsum(r1s[tid]);
        float b2 = wsum(r2s[tid]);
        float c = wsum(r3s[tid]);
        if (tid == 0) { fin[0] = a; fin[1] = b2; fin[2] = c; }
    }
    __syncthreads();
    if (tid < 64) {
        float mean = fin[0] * (1.f/64.f);
        float var  = fin[1] * (1.f/64.f) - mean*mean;
        float inv  = rsqrtf(var + EPSc);
        float on = fmaf((so[tid] - mean)*inv, gn_w[jb + tid], gn_b[jb + tid]);
        size_t lv = (((size_t)eb*NC + (NC-1))*L + 0)*H + jb + tid;  // vv at t=T-1
        on = fmaf(fin[2], g_NV[lv].y, on);
        g_o[eb*H + jb + tid] = on * g_glast[eb*H + jb + tid];
    }
    // ---- fused output GEMV: last head-block for this eb does out = g_o @ Wo^T ----
    __threadfence();
    if (tid == 0) sOld = atomicAdd(&g_cnt[eb], 1);
    __syncthreads();
    if (sOld == 3) {
        __threadfence();
        float* os = &osbuf[0][0];     // 256 contiguous floats
        os[tid] = g_o[eb*H + tid];
        __syncthreads();
        float acc = 0.f;
        const float4* __restrict__ Wrow = (const float4*)(Wo + tid*H);
        #pragma unroll 16
        for (int k4 = 0; k4 < 64; k4++) {
            float4 w4 = Wrow[k4];
            acc += os[4*k4]*w4.x + os[4*k4+1]*w4.y + os[4*k4+2]*w4.z + os[4*k4+3]*w4.w;
        }
        out[eb*H + tid] = acc;
    }
}

// ---------------- launch ----------------
extern "C" void kernel_launch(void* const* d_in, const int* in_sizes, int n_in,
                              void* d_out, int out_size) {
    const float* query   = (const float*)d_in[0];
    const float* keyval  = (const float*)d_in[1];
    const float* v_first = (const float*)d_in[2];
    const float* x_r = (const float*)d_in[3];
    const float* x_w = (const float*)d_in[4];
    const float* x_k = (const float*)d_in[5];
    const float* x_v = (const float*)d_in[6];
    const float* x_a = (const float*)d_in[7];
    const float* x_g = (const float*)d_in[8];
    const float* w0  = (const float*)d_in[9];
    const float* w1  = (const float*)d_in[10];
    const float* w2  = (const float*)d_in[11];
    const float* a0  = (const float*)d_in[12];
    const float* a1  = (const float*)d_in[13];
    const float* a2  = (const float*)d_in[14];
    const float* v0  = (const float*)d_in[15];
    const float* v1  = (const float*)d_in[16];
    const float* v2  = (const float*)d_in[17];
    const float* g1  = (const float*)d_in[18];
    const float* g2  = (const float*)d_in[19];
    const float* k_k = (const float*)d_in[20];
    const float* k_a = (const float*)d_in[21];
    const float* r_k = (const float*)d_in[22];
    const float* Wr  = (const float*)d_in[23];
    const float* Wk  = (const float*)d_in[24];
    const float* Wv  = (const float*)d_in[25];
    const float* Wo  = (const float*)d_in[26];
    const float* gn_w = (const float*)d_in[27];
    const float* gn_b = (const float*)d_in[28];
    float* out = (float*)d_out;

    k_prep<<<BT + EB + 128, 256>>>(keyval, query, x_k, x_v, x_w, x_a, x_r, x_g,
                                   w1, v1, a1, v2, a2, v0, g1, g2, Wr, Wk, Wv);
    k_chunk<<<dim3(NC, EB), 256>>>(v_first, w2, w0, a0, k_a, k_k);
    k_scan<<<EB*NH, 256>>>(r_k, gn_w, gn_b, Wo, out);
    (void)in_sizes; (void)n_in; (void)out_size;
}

// round 16
// speedup vs baseline: 1.1165x; 1.1165x over previous
#include <cuda_runtime.h>
#include <math.h>

#define H   256
#define HD  64
#define NH  4
#define Bb  2
#define Qq  8
#define Tt  512
#define L   16           // chunk length (timesteps)
#define NC  32           // Tt / L
#define EB  16
#define BT  1024
#define NEGc (-0.6065306597126334f)
#define EPSc 0.00064f

// ---------------- scratch (device globals; no allocations) ----------------
__device__ float g_K  [BT*H];
__device__ float g_Vb [BT*H];
__device__ float g_sigv[BT*H];
__device__ float g_hA [BT*H];
__device__ float g_Hw1[BT*32];
__device__ float g_qw1[EB*32];
__device__ float g_qA [EB*H];
__device__ float g_rlast[EB*H];
__device__ float g_glast[EB*H];
__device__ float g_o  [EB*H];
__device__ int   g_cnt[EB];
// chunked scan inputs
__device__ float  g_W [(size_t)EB*NC*L*H];   // Ŵ_i = P_i ∘ kf
__device__ float  g_Bv[(size_t)EB*NC*L*H];   // B̂_i = P_i ∘ bv
__device__ float2 g_NV[(size_t)EB*NC*L*H];   // {ñ_m, vv}
__device__ float  g_Ep[(size_t)EB*NC*H];     // Ê = P_L
__device__ float2 g_Q2[(size_t)EB*NC*NH*L*L]; // {QK, QB}

__device__ __forceinline__ float sigmoidf_(float x) { return 1.f / (1.f + __expf(-x)); }

__device__ __forceinline__ float wsum(float v) {
    #pragma unroll
    for (int o = 16; o; o >>= 1) v += __shfl_xor_sync(0xffffffffu, v, o);
    return v;
}

// ---------------- k1: GEMM tiles FIRST, then per-bt chains, then per-eb chains ----------------
// Single 17KB shared buffer aliased by all three paths.
#define NGB 128
__global__ void __launch_bounds__(256) k_prep(
        const float* __restrict__ keyval, const float* __restrict__ query,
        const float* __restrict__ x_k, const float* __restrict__ x_v,
        const float* __restrict__ x_w, const float* __restrict__ x_a,
        const float* __restrict__ x_r, const float* __restrict__ x_g,
        const float* __restrict__ w1, const float* __restrict__ v1,
        const float* __restrict__ a1, const float* __restrict__ v2,
        const float* __restrict__ a2, const float* __restrict__ v0,
        const float* __restrict__ g1, const float* __restrict__ g2,
        const float* __restrict__ Wr, const float* __restrict__ Wk,
        const float* __restrict__ Wv) {
    __shared__ float smemU[2*64*33];     // 16.9 KB, shared by all paths
    int blk = blockIdx.x;
    int j = threadIdx.x;
    if (blk < NGB) {
        // ---- K / Vb GEMM tile (launched first: overlaps the short blocks) ----
        float (*As)[33] = (float(*)[33])smemU;
        float (*Ws)[33] = (float(*)[33])(smemU + 64*33);
        int gb = blk;
        int bmI = gb & 15, bnI = (gb >> 4) & 3, z = gb >> 6;
        const float* __restrict__ xm = z ? x_v : x_k;
        const float* __restrict__ W  = z ? Wv  : Wk;
        float* __restrict__ C = z ? g_Vb : g_K;
        int tid = j;
        int tx = tid & 15, ty = tid >> 4;
        int bm = bmI * 64, bn = bnI * 64;
        float acc[4][4] = {};
        #pragma unroll 1
        for (int k0 = 0; k0 < H; k0 += 32) {
            #pragma unroll
            for (int l = tid; l < 64*32; l += 256) {
                int r = l >> 5, c = l & 31;
                int m = bm + r, kg = k0 + c;
                int t = m & (Tt - 1);
                float hs = keyval[m*H + kg];
                float hp = (t > 0) ? keyval[(m-1)*H + kg] : 0.f;
                As[r][c] = fmaf(hp - hs, __ldg(&xm[kg]), hs);
                Ws[r][c] = W[(bn + r)*H + kg];
            }
            __syncthreads();
            #pragma unroll
            for (int kk = 0; kk < 32; kk++) {
                float a_[4], w_[4];
                #pragma unroll
                for (int i = 0; i < 4; i++) { a_[i] = As[ty + 16*i][kk]; w_[i] = Ws[tx + 16*i][kk]; }
                #pragma unroll
                for (int i = 0; i < 4; i++)
                    #pragma unroll
                    for (int jj = 0; jj < 4; jj++) acc[i][jj] = fmaf(a_[i], w_[jj], acc[i][jj]);
            }
            __syncthreads();
        }
        #pragma unroll
        for (int i = 0; i < 4; i++)
            #pragma unroll
            for (int jj = 0; jj < 4; jj++)
                C[(bm + ty + 16*i)*H + (bn + tx + 16*jj)] = acc[i][jj];
    } else if (blk < NGB + BT) {
        // ---- per-(b,t) small chains ----
        float* s0 = smemU;             // 256
        float* s1 = smemU + 256;
        float* s2 = smemU + 512;
        float (*red)[8][32] = (float(*)[8][32])(smemU + 1024);  // 3*8*32 = 768
        float (*mid)[32]    = (float(*)[32])(smemU + 2048);     // 3*32
        int w = j >> 5, ln = j & 31;
        int bt = blk - NGB, t = bt & (Tt - 1);
        float hs = keyval[bt*H + j];
        float hp = (t > 0) ? keyval[(bt-1)*H + j] : 0.f;
        s0[j] = fmaf(hp - hs, x_v[j], hs);   // xv
        s1[j] = hs * (1.f - x_w[j]);         // xwh
        s2[j] = hs * (1.f - x_a[j]);         // xah
        __syncthreads();
        int kbase = w * 32;
        float pw = 0.f, pv = 0.f, pa = 0.f;
        #pragma unroll
        for (int kk = 0; kk < 32; kk++) {
            int k = kbase + kk;
            pw = fmaf(s1[k], w1[k*32 + ln], pw);
            pv = fmaf(s0[k], v1[k*32 + ln], pv);
            pa = fmaf(s2[k], a1[k*32 + ln], pa);
        }
        red[0][w][ln] = pw; red[1][w][ln] = pv; red[2][w][ln] = pa;
        __syncthreads();
        if (j < 96) {
            int m = j >> 5, d = j & 31;
            float s = 0.f;
            #pragma unroll
            for (int ww = 0; ww < 8; ww++) s += red[m][ww][d];
            mid[m][d] = s;
            if (m == 0) g_Hw1[bt*32 + d] = s;
        }
        __syncthreads();
        float av = 0.f, aa = 0.f;
        #pragma unroll
        for (int d = 0; d < 32; d++) {
            av = fmaf(mid[1][d], v2[d*H + j], av);
            aa = fmaf(mid[2][d], a2[d*H + j], aa);
        }
        g_sigv[bt*H + j] = sigmoidf_(av + v0[j]);
        g_hA[bt*H + j]   = aa;
    } else {
        // ---- per-eb small chains ----
        float* s0 = smemU;
        float* s1 = smemU + 256;
        float* s2 = smemU + 512;
        float* s3 = smemU + 768;
        float (*red)[8][32] = (float(*)[8][32])(smemU + 1024);  // 4*8*32 = 1024
        float (*mid)[32]    = (float(*)[32])(smemU + 2048);     // 4*32
        int w = j >> 5, ln = j & 31;
        int eb = blk - (NGB + BT); int b = eb >> 3;
        if (j == 0) g_cnt[eb] = 0;            // reset ticket each launch
        float qv  = query[eb*H + j];
        float hsL = keyval[(b*Tt + Tt - 1)*H + j];
        s0[j] = fmaf(qv - hsL, x_r[j], hsL);  // xr
        s1[j] = fmaf(qv - hsL, x_g[j], hsL);  // xg
        s2[j] = qv * x_w[j];                  // xw (query part)
        s3[j] = qv * x_a[j];                  // xa (query part)
        __syncthreads();
        int kbase = w * 32;
        float pw = 0.f, pa = 0.f, pg0 = 0.f, pg1 = 0.f;
        #pragma unroll
        for (int kk = 0; kk < 32; kk++) {
            int k = kbase + kk;
            pw  = fmaf(s2[k], w1[k*32 + ln], pw);
            pa  = fmaf(s3[k], a1[k*32 + ln], pa);
            pg0 = fmaf(s1[k], g1[k*64 + ln], pg0);
            pg1 = fmaf(s1[k], g1[k*64 + 32 + ln], pg1);
        }
        red[0][w][ln] = pw; red[1][w][ln] = pa; red[2][w][ln] = pg0; red[3][w][ln] = pg1;
        __syncthreads();
        if (j < 128) {
            int m = j >> 5, d = j & 31;
            float s = 0.f;
            #pragma unroll
            for (int ww = 0; ww < 8; ww++) s += red[m][ww][d];
            if      (m == 0) g_qw1[eb*32 + d] = s;
            else if (m == 1) mid[1][d] = s;               // ta
            else if (m == 2) mid[2][d] = sigmoidf_(s);    // tg[0:32]
            else             mid[3][d] = sigmoidf_(s);    // tg[32:64]
        }
        __syncthreads();
        float aa = 0.f, gg = 0.f;
        #pragma unroll
        for (int d = 0; d < 32; d++) {
            aa = fmaf(mid[1][d], a2[d*H + j], aa);
            gg = fmaf(mid[2][d], g2[d*H + j], gg);
        }
        #pragma unroll
        for (int d = 0; d < 32; d++) gg = fmaf(mid[3][d], g2[(32 + d)*H + j], gg);
        g_qA[eb*H + j]    = aa;
        g_glast[eb*H + j] = gg;
        float acc = 0.f;
        const float4* __restrict__ Wrow = (const float4*)(Wr + j*H);
        #pragma unroll 16
        for (int k4 = 0; k4 < 64; k4++) {
            float4 wv = Wrow[k4];
            acc += s0[4*k4]*wv.x + s0[4*k4+1]*wv.y + s0[4*k4+2]*wv.z + s0[4*k4+3]*wv.w;
        }
        g_rlast[eb*H + j] = acc;
    }
}

// ---------------- k2: per-(eb, chunk) precompute (hoisted norms, sync-free loop) ----------------
__global__ void __launch_bounds__(256) k_chunk(
        const float* __restrict__ v_first, const float* __restrict__ w2,
        const float* __restrict__ w0, const float* __restrict__ a0,
        const float* __restrict__ k_a, const float* __restrict__ k_k) {
    int p = blockIdx.x, eb = blockIdx.y;
    int b = eb >> 3;
    int j = threadIdx.x;             // 256
    __shared__ float th[L][32];
    __shared__ float sN[L][H+1];     // phase A: kkv; later: Ñ
    __shared__ float sW[L][H+1];     // Ŵ, then B̂ reload
    __shared__ float invn[L][NH];
    // Phase A: kkv for all L timesteps (coalesced), th loads
    for (int idx = j; idx < L*H; idx += 256) {
        int i = idx >> 8, d = idx & 255;
        int t = p*L + (L-1) - i;
        sN[i][d] = g_K[(b*Tt + t)*H + d] * __ldg(&k_k[d]);
    }
    for (int idx = j; idx < L*32; idx += 256) {
        int i = idx >> 5, d = idx & 31;
        int t = p*L + (L-1) - i;
        th[i][d] = tanhf(g_Hw1[(b*Tt + t)*32 + d] + g_qw1[eb*32 + d]);
    }
    __syncthreads();
    // Phase B: all 64 head-norms in parallel (4 lanes per (i,head))
    {
        int i = j >> 4;          // 0..15
        int hh = (j >> 2) & 3;   // 0..3
        int part = j & 3;        // 0..3
        int base = hh*64 + part*16;
        float a = 0.f;
        #pragma unroll
        for (int d = 0; d < 16; d++) { float x = sN[i][base + d]; a = fmaf(x, x, a); }
        a += __shfl_xor_sync(0xffffffffu, a, 1);
        a += __shfl_xor_sync(0xffffffffu, a, 2);
        if (part == 0) invn[i][hh] = 1.f / fmaxf(sqrtf(a), 1e-12f);
    }
    __syncthreads();
    // Phase C: serial i-loop, NO block syncs inside
    float w0j = w0[j], a0j = a0[j], kaj = k_a[j], qAj = g_qA[eb*H + j];
    float rkk = 1.f / k_k[j];        // k_k in [0.7, 1.0]
    float w2c[32];
    #pragma unroll
    for (int d = 0; d < 32; d++) w2c[d] = w2[d*H + j];
    int head = j >> 6;
    float P = 1.f;
    #pragma unroll 1
    for (int i = 0; i < L; i++) {
        int t = p*L + (L-1) - i;
        int bt = b*Tt + t;
        float ac = 0.f;
        #pragma unroll
        for (int d = 0; d < 32; d++) ac = fmaf(th[i][d], w2c[d], ac);
        float ew = __expf(NEGc * sigmoidf_(w0j + ac));
        float kkv = sN[i][j];
        float kk = kkv * invn[i][head];
        float Kv = kkv * rkk;
        float a4 = sigmoidf_(a0j + g_hA[bt*H + j] + qAj);
        float kf = Kv * fmaf(a4 - 1.f, kaj, 1.f);
        float bvv = kk * a4;
        float vb = g_Vb[bt*H + j], sv = g_sigv[bt*H + j];
        float vv = fmaf(v_first[((size_t)eb*Tt + t)*H + j] - vb, sv, vb);
        float Wi = P * kf;
        float Bi = P * bvv;
        float Ni = kk / (P * ew);      // P_{i+1} = P * ew
        sN[i][j] = Ni; sW[i][j] = Wi;
        size_t o = (((size_t)eb*NC + p)*L + i)*H + j;
        g_W[o] = Wi; g_Bv[o] = Bi;
        g_NV[o] = make_float2(Ni, vv);
        P *= ew;
    }
    g_Ep[((size_t)eb*NC + p)*H + j] = P;
    __syncthreads();
    // QK[m][i] = ñ_m · Ŵ_i (per head, strictly m < i)
    size_t qbase = (((size_t)eb*NC + p)*NH) * (L*L);
    for (int idx = j; idx < NH*120; idx += 256) {
        int hh = idx / 120;
        int r = idx % 120;
        int i = (int)((1.0f + sqrtf(1.0f + 8.0f*(float)r)) * 0.5f);
        int tri = (i*(i-1)) >> 1;
        if (r < tri) { i--; tri = (i*(i-1)) >> 1; }
        else if (r >= tri + i) { i++; tri = (i*(i-1)) >> 1; }
        int m = r - tri;
        int base = hh * 64;
        float acc = 0.f;
        #pragma unroll
        for (int d = 0; d < 64; d++) acc = fmaf(sN[m][base+d], sW[i][base+d], acc);
        g_Q2[qbase + (size_t)hh*(L*L) + m*L + i].x = acc;
    }
    __syncthreads();
    // reload B̂ into sW (L2-hot), then QB
    for (int idx = j; idx < L*H; idx += 256) {
        int i = idx >> 8, d = idx & 255;
        sW[i][d] = g_Bv[(((size_t)eb*NC + p)*L + i)*H + d];
    }
    __syncthreads();
    for (int idx = j; idx < NH*120; idx += 256) {
        int hh = idx / 120;
        int r = idx % 120;
        int i = (int)((1.0f + sqrtf(1.0f + 8.0f*(float)r)) * 0.5f);
        int tri = (i*(i-1)) >> 1;
        if (r < tri) { i--; tri = (i*(i-1)) >> 1; }
        else if (r >= tri + i) { i++; tri = (i*(i-1)) >> 1; }
        int m = r - tri;
        int base = hh * 64;
        float acc = 0.f;
        #pragma unroll
        for (int d = 0; d < 64; d++) acc = fmaf(sN[m][base+d], sW[i][base+d], acc);
        g_Q2[qbase + (size_t)hh*(L*L) + m*L + i].y = acc;
    }
}

// ---------------- k3: chunked backward scan (3 syncs/round) + fused Wo GEMV ----------------
__global__ void __launch_bounds__(256) k_scan(const float* __restrict__ r_k,
                        const float* __restrict__ gn_w, const float* __restrict__ gn_b,
                        const float* __restrict__ Wo, float* __restrict__ out) {
    int blk = blockIdx.x;
    int eb = blk >> 2, h = blk & 3;
    int tid = threadIdx.x;
    int jb = h * 64;
    __shared__ float su[64], so[64];
    __shared__ float rs[L], es[L], cs[L], ss[L];
    __shared__ float osbuf[4][64];
    __shared__ float r1s[64], r2s[64], r3s[64];
    __shared__ float fin[3];
    __shared__ int sOld;
    if (tid < 64) { su[tid] = g_rlast[eb*H + jb + tid]; so[tid] = 0.f; }
    __syncthreads();
    int i16 = tid >> 4;
    int jg  = tid & 15;
    float4 wv, bvv;
    {
        size_t cb0 = ((size_t)eb*NC + (NC-1))*L*H + jb;
        wv  = *((const float4*)(g_W  + cb0 + (size_t)i16*H) + jg);
        bvv = *((const float4*)(g_Bv + cb0 + (size_t)i16*H) + jg);
    }
    #pragma unroll 1
    for (int p = NC - 1; p >= 0; --p) {
        size_t cb = ((size_t)eb*NC + p)*L*H + jb;
        float2 nv[16];
        float Ereg = 0.f;
        if (tid < 64) {
            #pragma unroll
            for (int m = 0; m < L; m++) nv[m] = g_NV[cb + (size_t)m*H + tid];
            Ereg = g_Ep[((size_t)eb*NC + p)*H + jb + tid];
        }
        float2 qcol[L];
        if (tid < 16) {
            size_t qb = (((size_t)eb*NC + p)*NH + h)*(L*L);
            #pragma unroll
            for (int m = 0; m < L; m++) qcol[m] = g_Q2[qb + m*L + tid];
        }
        float u0 = su[jg*4], u1 = su[jg*4+1], u2 = su[jg*4+2], u3 = su[jg*4+3];
        float pr = u0*wv.x + u1*wv.y + u2*wv.z + u3*wv.w;
        float pe = u0*bvv.x + u1*bvv.y + u2*bvv.z + u3*bvv.w;
        if (p > 0) {
            size_t cbn = ((size_t)eb*NC + (p-1))*L*H + jb;
            wv  = *((const float4*)(g_W  + cbn + (size_t)i16*H) + jg);
            bvv = *((const float4*)(g_Bv + cbn + (size_t)i16*H) + jg);
        }
        #pragma unroll
        for (int off = 8; off; off >>= 1) {
            pr += __shfl_xor_sync(0xffffffffu, pr, off);
            pe += __shfl_xor_sync(0xffffffffu, pe, off);
        }
        if (jg == 0) { rs[i16] = pr; es[i16] = pe; }
        __syncthreads();
        if (tid < 16) {
            float c = rs[tid], s = es[tid];
            #pragma unroll
            for (int m = 0; m < L-1; m++) {
                float sm = __shfl_sync(0x0000ffffu, s, m, 16);
                if (tid > m) {
                    c = fmaf(-sm, qcol[m].x, c);
                    s = fmaf(-sm, qcol[m].y, s);
                }
            }
            cs[tid] = c; ss[tid] = s;
        }
        __syncthreads();
        if (tid < 64) {
            float accO = 0.f, accU = 0.f;
            #pragma unroll
            for (int m = 0; m < L; m++) {
                accO = fmaf(cs[m], nv[m].y, accO);
                accU = fmaf(ss[m], nv[m].x, accU);
            }
            so[tid] += accO;
            su[tid] = Ereg * (su[tid] - accU);
        }
        __syncthreads();
    }
    // epilogue: groupnorm + residual + gate
    if (tid < 64) {
        float o = so[tid];
        r1s[tid] = o;
        r2s[tid] = o*o;
        size_t lw = (((size_t)eb*NC + (NC-1))*L + 0)*H + jb + tid;
        r3s[tid] = g_rlast[eb*H + jb + tid] * g_W[lw] * r_k[jb + tid];
    }
    __syncthreads();
    if (tid < 32) {
        r1s[tid] += r1s[tid + 32];
        r2s[tid] += r2s[tid + 32];
        r3s[tid] += r3s[tid + 32];
        float a = wsum(r1s[tid]);
        float b2 = wsum(r2s[tid]);
        float c = wsum(r3s[tid]);
        if (tid == 0) { fin[0] = a; fin[1] = b2; fin[2] = c; }
    }
    __syncthreads();
    if (tid < 64) {
        float mean = fin[0] * (1.f/64.f);
        float var  = fin[1] * (1.f/64.f) - mean*mean;
        float inv  = rsqrtf(var + EPSc);
        float on = fmaf((so[tid] - mean)*inv, gn_w[jb + tid], gn_b[jb + tid]);
        size_t lv = (((size_t)eb*NC + (NC-1))*L + 0)*H + jb + tid;
        on = fmaf(fin[2], g_NV[lv].y, on);
        g_o[eb*H + jb + tid] = on * g_glast[eb*H + jb + tid];
    }
    // fused output GEMV: last head-block for this eb does out = g_o @ Wo^T
    __threadfence();
    if (tid == 0) sOld = atomicAdd(&g_cnt[eb], 1);
    __syncthreads();
    if (sOld == 3) {
        __threadfence();
        float* os = &osbuf[0][0];
        os[tid] = g_o[eb*H + tid];
        __syncthreads();
        float acc = 0.f;
        const float4* __restrict__ Wrow = (const float4*)(Wo + tid*H);
        #pragma unroll 16
        for (int k4 = 0; k4 < 64; k4++) {
            float4 w4 = Wrow[k4];
            acc += os[4*k4]*w4.x + os[4*k4+1]*w4.y + os[4*k4+2]*w4.z + os[4*k4+3]*w4.w;
        }
        out[eb*H + tid] = acc;
    }
}

// ---------------- launch ----------------
extern "C" void kernel_launch(void* const* d_in, const int* in_sizes, int n_in,
                              void* d_out, int out_size) {
    const float* query   = (const float*)d_in[0];
    const float* keyval  = (const float*)d_in[1];
    const float* v_first = (const float*)d_in[2];
    const float* x_r = (const float*)d_in[3];
    const float* x_w = (const float*)d_in[4];
    const float* x_k = (const float*)d_in[5];
    const float* x_v = (const float*)d_in[6];
    const float* x_a = (const float*)d_in[7];
    const float* x_g = (const float*)d_in[8];
    const float* w0  = (const float*)d_in[9];
    const float* w1  = (const float*)d_in[10];
    const float* w2  = (const float*)d_in[11];
    const float* a0  = (const float*)d_in[12];
    const float* a1  = (const float*)d_in[13];
    const float* a2  = (const float*)d_in[14];
    const float* v0  = (const float*)d_in[15];
    const float* v1  = (const float*)d_in[16];
    const float* v2  = (const float*)d_in[17];
    const float* g1  = (const float*)d_in[18];
    const float* g2  = (const float*)d_in[19];
    const float* k_k = (const float*)d_in[20];
    const float* k_a = (const float*)d_in[21];
    const float* r_k = (const float*)d_in[22];
    const float* Wr  = (const float*)d_in[23];
    const float* Wk  = (const float*)d_in[24];
    const float* Wv  = (const float*)d_in[25];
    const float* Wo  = (const float*)d_in[26];
    const float* gn_w = (const float*)d_in[27];
    const float* gn_b = (const float*)d_in[28];
    float* out = (float*)d_out;

    k_prep<<<NGB + BT + EB, 256>>>(keyval, query, x_k, x_v, x_w, x_a, x_r, x_g,
                                   w1, v1, a1, v2, a2, v0, g1, g2, Wr, Wk, Wv);
    k_chunk<<<dim3(NC, EB), 256>>>(v_first, w2, w0, a0, k_a, k_k);
    k_scan<<<EB*NH, 256>>>(r_k, gn_w, gn_b, Wo, out);
    (void)in_sizes; (void)n_in; (void)out_size;
}

// round 17
// speedup vs baseline: 1.1344x; 1.0161x over previous
#include <cuda_runtime.h>
#include <math.h>

#define H   256
#define HD  64
#define NH  4
#define Bb  2
#define Qq  8
#define Tt  512
#define L   16           // chunk length (timesteps)
#define NC  32           // Tt / L
#define EB  16
#define BT  1024
#define NEGc (-0.6065306597126334f)
#define EPSc 0.00064f

// ---------------- scratch (device globals; no allocations) ----------------
__device__ float g_K  [BT*H];
__device__ float g_Vb [BT*H];
__device__ float g_sigv[BT*H];
__device__ float g_hA [BT*H];
__device__ float g_Hw1[BT*32];
__device__ float g_qw1[EB*32];
__device__ float g_qA [EB*H];
__device__ float g_rlast[EB*H];
__device__ float g_glast[EB*H];
__device__ float g_o  [EB*H];
__device__ int   g_cnt[EB];
// chunked scan inputs
__device__ float  g_W [(size_t)EB*NC*L*H];   // Ŵ_i = P_i ∘ kf
__device__ float  g_Bv[(size_t)EB*NC*L*H];   // B̂_i = P_i ∘ bv
__device__ float2 g_NV[(size_t)EB*NC*L*H];   // {ñ_m, vv}
__device__ float  g_Ep[(size_t)EB*NC*H];     // Ê = P_L
__device__ float2 g_Q2[(size_t)EB*NC*NH*L*L]; // {QK, QB}

__device__ __forceinline__ float sigmoidf_(float x) { return 1.f / (1.f + __expf(-x)); }

__device__ __forceinline__ float wsum(float v) {
    #pragma unroll
    for (int o = 16; o; o >>= 1) v += __shfl_xor_sync(0xffffffffu, v, o);
    return v;
}

// ---------------- k1: GEMM tiles first, then 4-row-batched per-bt chains, then per-eb ----------------
#define NGB 128
#define NBTB 256    // per-bt blocks (4 rows each)
__global__ void __launch_bounds__(256) k_prep(
        const float* __restrict__ keyval, const float* __restrict__ query,
        const float* __restrict__ x_k, const float* __restrict__ x_v,
        const float* __restrict__ x_w, const float* __restrict__ x_a,
        const float* __restrict__ x_r, const float* __restrict__ x_g,
        const float* __restrict__ w1, const float* __restrict__ v1,
        const float* __restrict__ a1, const float* __restrict__ v2,
        const float* __restrict__ a2, const float* __restrict__ v0,
        const float* __restrict__ g1, const float* __restrict__ g2,
        const float* __restrict__ Wr, const float* __restrict__ Wk,
        const float* __restrict__ Wv) {
    __shared__ float smemU[6528];     // 25.5 KB union
    int blk = blockIdx.x;
    int j = threadIdx.x;
    if (blk < NGB) {
        // ---- K / Vb GEMM tile ----
        float (*As)[33] = (float(*)[33])smemU;
        float (*Ws)[33] = (float(*)[33])(smemU + 64*33);
        int gb = blk;
        int bmI = gb & 15, bnI = (gb >> 4) & 3, z = gb >> 6;
        const float* __restrict__ xm = z ? x_v : x_k;
        const float* __restrict__ W  = z ? Wv  : Wk;
        float* __restrict__ C = z ? g_Vb : g_K;
        int tid = j;
        int tx = tid & 15, ty = tid >> 4;
        int bm = bmI * 64, bn = bnI * 64;
        float acc[4][4] = {};
        #pragma unroll 1
        for (int k0 = 0; k0 < H; k0 += 32) {
            #pragma unroll
            for (int l = tid; l < 64*32; l += 256) {
                int r = l >> 5, c = l & 31;
                int m = bm + r, kg = k0 + c;
                int t = m & (Tt - 1);
                float hs = keyval[m*H + kg];
                float hp = (t > 0) ? keyval[(m-1)*H + kg] : 0.f;
                As[r][c] = fmaf(hp - hs, __ldg(&xm[kg]), hs);
                Ws[r][c] = W[(bn + r)*H + kg];
            }
            __syncthreads();
            #pragma unroll
            for (int kk = 0; kk < 32; kk++) {
                float a_[4], w_[4];
                #pragma unroll
                for (int i = 0; i < 4; i++) { a_[i] = As[ty + 16*i][kk]; w_[i] = Ws[tx + 16*i][kk]; }
                #pragma unroll
                for (int i = 0; i < 4; i++)
                    #pragma unroll
                    for (int jj = 0; jj < 4; jj++) acc[i][jj] = fmaf(a_[i], w_[jj], acc[i][jj]);
            }
            __syncthreads();
        }
        #pragma unroll
        for (int i = 0; i < 4; i++)
            #pragma unroll
            for (int jj = 0; jj < 4; jj++)
                C[(bm + ty + 16*i)*H + (bn + tx + 16*jj)] = acc[i][jj];
    } else if (blk < NGB + NBTB) {
        // ---- per-(b,t) small chains, 4 rows per block ----
        float* s0 = smemU;               // [4][256]
        float* s1 = smemU + 1024;
        float* s2 = smemU + 2048;
        float* red = smemU + 3072;       // [3][4][8][32]
        float* mid = smemU + 6144;       // [3][4][32]
        int w = j >> 5, ln = j & 31;
        int btb = (blk - NGB) * 4;
        float xvj = x_v[j], xwj = 1.f - x_w[j], xaj = 1.f - x_a[j];
        #pragma unroll
        for (int row = 0; row < 4; row++) {
            int bt = btb + row, t = bt & (Tt - 1);
            float hs = keyval[bt*H + j];
            float hp = (t > 0) ? keyval[(bt-1)*H + j] : 0.f;
            s0[row*256 + j] = fmaf(hp - hs, xvj, hs);
            s1[row*256 + j] = hs * xwj;
            s2[row*256 + j] = hs * xaj;
        }
        __syncthreads();
        int kbase = w * 32;
        float pw[4] = {}, pv[4] = {}, pa[4] = {};
        #pragma unroll
        for (int kk = 0; kk < 32; kk++) {
            int k = kbase + kk;
            float w1v = w1[k*32 + ln], v1v = v1[k*32 + ln], a1v = a1[k*32 + ln];
            #pragma unroll
            for (int row = 0; row < 4; row++) {
                pw[row] = fmaf(s1[row*256 + k], w1v, pw[row]);
                pv[row] = fmaf(s0[row*256 + k], v1v, pv[row]);
                pa[row] = fmaf(s2[row*256 + k], a1v, pa[row]);
            }
        }
        #pragma unroll
        for (int row = 0; row < 4; row++) {
            red[((0*4 + row)*8 + w)*32 + ln] = pw[row];
            red[((1*4 + row)*8 + w)*32 + ln] = pv[row];
            red[((2*4 + row)*8 + w)*32 + ln] = pa[row];
        }
        __syncthreads();
        if (j < 96) {
            int m = j >> 5, d = j & 31;
            #pragma unroll
            for (int row = 0; row < 4; row++) {
                float s = 0.f;
                #pragma unroll
                for (int ww = 0; ww < 8; ww++) s += red[((m*4 + row)*8 + ww)*32 + d];
                mid[(m*4 + row)*32 + d] = s;
                if (m == 0) g_Hw1[(btb + row)*32 + d] = s;
            }
        }
        __syncthreads();
        float av[4] = {}, aa[4] = {};
        #pragma unroll
        for (int d = 0; d < 32; d++) {
            float v2d = v2[d*H + j], a2d = a2[d*H + j];
            #pragma unroll
            for (int row = 0; row < 4; row++) {
                av[row] = fmaf(mid[(1*4 + row)*32 + d], v2d, av[row]);
                aa[row] = fmaf(mid[(2*4 + row)*32 + d], a2d, aa[row]);
            }
        }
        float v0j = v0[j];
        #pragma unroll
        for (int row = 0; row < 4; row++) {
            int bt = btb + row;
            g_sigv[bt*H + j] = sigmoidf_(av[row] + v0j);
            g_hA[bt*H + j]   = aa[row];
        }
    } else {
        // ---- per-eb small chains ----
        float* s0 = smemU;
        float* s1 = smemU + 256;
        float* s2 = smemU + 512;
        float* s3 = smemU + 768;
        float (*red)[8][32] = (float(*)[8][32])(smemU + 1024);
        float (*mid)[32]    = (float(*)[32])(smemU + 2048);
        int w = j >> 5, ln = j & 31;
        int eb = blk - (NGB + NBTB); int b = eb >> 3;
        if (j == 0) g_cnt[eb] = 0;
        float qv  = query[eb*H + j];
        float hsL = keyval[(b*Tt + Tt - 1)*H + j];
        s0[j] = fmaf(qv - hsL, x_r[j], hsL);
        s1[j] = fmaf(qv - hsL, x_g[j], hsL);
        s2[j] = qv * x_w[j];
        s3[j] = qv * x_a[j];
        __syncthreads();
        int kbase = w * 32;
        float pw = 0.f, pa = 0.f, pg0 = 0.f, pg1 = 0.f;
        #pragma unroll
        for (int kk = 0; kk < 32; kk++) {
            int k = kbase + kk;
            pw  = fmaf(s2[k], w1[k*32 + ln], pw);
            pa  = fmaf(s3[k], a1[k*32 + ln], pa);
            pg0 = fmaf(s1[k], g1[k*64 + ln], pg0);
            pg1 = fmaf(s1[k], g1[k*64 + 32 + ln], pg1);
        }
        red[0][w][ln] = pw; red[1][w][ln] = pa; red[2][w][ln] = pg0; red[3][w][ln] = pg1;
        __syncthreads();
        if (j < 128) {
            int m = j >> 5, d = j & 31;
            float s = 0.f;
            #pragma unroll
            for (int ww = 0; ww < 8; ww++) s += red[m][ww][d];
            if      (m == 0) g_qw1[eb*32 + d] = s;
            else if (m == 1) mid[1][d] = s;
            else if (m == 2) mid[2][d] = sigmoidf_(s);
            else             mid[3][d] = sigmoidf_(s);
        }
        __syncthreads();
        float aa = 0.f, gg = 0.f;
        #pragma unroll
        for (int d = 0; d < 32; d++) {
            aa = fmaf(mid[1][d], a2[d*H + j], aa);
            gg = fmaf(mid[2][d], g2[d*H + j], gg);
        }
        #pragma unroll
        for (int d = 0; d < 32; d++) gg = fmaf(mid[3][d], g2[(32 + d)*H + j], gg);
        g_qA[eb*H + j]    = aa;
        g_glast[eb*H + j] = gg;
        float acc = 0.f;
        const float4* __restrict__ Wrow = (const float4*)(Wr + j*H);
        #pragma unroll 16
        for (int k4 = 0; k4 < 64; k4++) {
            float4 wv = Wrow[k4];
            acc += s0[4*k4]*wv.x + s0[4*k4+1]*wv.y + s0[4*k4+2]*wv.z + s0[4*k4+3]*wv.w;
        }
        g_rlast[eb*H + j] = acc;
    }
}

// ---------------- k2: per-(eb, chunk) precompute (hoisted norms, sync-free loop) ----------------
__global__ void __launch_bounds__(256) k_chunk(
        const float* __restrict__ v_first, const float* __restrict__ w2,
        const float* __restrict__ w0, const float* __restrict__ a0,
        const float* __restrict__ k_a, const float* __restrict__ k_k) {
    int p = blockIdx.x, eb = blockIdx.y;
    int b = eb >> 3;
    int j = threadIdx.x;
    __shared__ float th[L][32];
    __shared__ float sN[L][H+1];
    __shared__ float sW[L][H+1];
    __shared__ float invn[L][NH];
    for (int idx = j; idx < L*H; idx += 256) {
        int i = idx >> 8, d = idx & 255;
        int t = p*L + (L-1) - i;
        sN[i][d] = g_K[(b*Tt + t)*H + d] * __ldg(&k_k[d]);
    }
    for (int idx = j; idx < L*32; idx += 256) {
        int i = idx >> 5, d = idx & 31;
        int t = p*L + (L-1) - i;
        th[i][d] = tanhf(g_Hw1[(b*Tt + t)*32 + d] + g_qw1[eb*32 + d]);
    }
    __syncthreads();
    {
        int i = j >> 4;
        int hh = (j >> 2) & 3;
        int part = j & 3;
        int base = hh*64 + part*16;
        float a = 0.f;
        #pragma unroll
        for (int d = 0; d < 16; d++) { float x = sN[i][base + d]; a = fmaf(x, x, a); }
        a += __shfl_xor_sync(0xffffffffu, a, 1);
        a += __shfl_xor_sync(0xffffffffu, a, 2);
        if (part == 0) invn[i][hh] = 1.f / fmaxf(sqrtf(a), 1e-12f);
    }
    __syncthreads();
    float w0j = w0[j], a0j = a0[j], kaj = k_a[j], qAj = g_qA[eb*H + j];
    float rkk = 1.f / k_k[j];
    float w2c[32];
    #pragma unroll
    for (int d = 0; d < 32; d++) w2c[d] = w2[d*H + j];
    int head = j >> 6;
    float P = 1.f;
    #pragma unroll 1
    for (int i = 0; i < L; i++) {
        int t = p*L + (L-1) - i;
        int bt = b*Tt + t;
        float ac = 0.f;
        #pragma unroll
        for (int d = 0; d < 32; d++) ac = fmaf(th[i][d], w2c[d], ac);
        float ew = __expf(NEGc * sigmoidf_(w0j + ac));
        float kkv = sN[i][j];
        float kk = kkv * invn[i][head];
        float Kv = kkv * rkk;
        float a4 = sigmoidf_(a0j + g_hA[bt*H + j] + qAj);
        float kf = Kv * fmaf(a4 - 1.f, kaj, 1.f);
        float bvv = kk * a4;
        float vb = g_Vb[bt*H + j], sv = g_sigv[bt*H + j];
        float vv = fmaf(v_first[((size_t)eb*Tt + t)*H + j] - vb, sv, vb);
        float Wi = P * kf;
        float Bi = P * bvv;
        float Ni = kk / (P * ew);
        sN[i][j] = Ni; sW[i][j] = Wi;
        size_t o = (((size_t)eb*NC + p)*L + i)*H + j;
        g_W[o] = Wi; g_Bv[o] = Bi;
        g_NV[o] = make_float2(Ni, vv);
        P *= ew;
    }
    g_Ep[((size_t)eb*NC + p)*H + j] = P;
    __syncthreads();
    size_t qbase = (((size_t)eb*NC + p)*NH) * (L*L);
    for (int idx = j; idx < NH*120; idx += 256) {
        int hh = idx / 120;
        int r = idx % 120;
        int i = (int)((1.0f + sqrtf(1.0f + 8.0f*(float)r)) * 0.5f);
        int tri = (i*(i-1)) >> 1;
        if (r < tri) { i--; tri = (i*(i-1)) >> 1; }
        else if (r >= tri + i) { i++; tri = (i*(i-1)) >> 1; }
        int m = r - tri;
        int base = hh * 64;
        float acc = 0.f;
        #pragma unroll
        for (int d = 0; d < 64; d++) acc = fmaf(sN[m][base+d], sW[i][base+d], acc);
        g_Q2[qbase + (size_t)hh*(L*L) + m*L + i].x = acc;
    }
    __syncthreads();
    for (int idx = j; idx < L*H; idx += 256) {
        int i = idx >> 8, d = idx & 255;
        sW[i][d] = g_Bv[(((size_t)eb*NC + p)*L + i)*H + d];
    }
    __syncthreads();
    for (int idx = j; idx < NH*120; idx += 256) {
        int hh = idx / 120;
        int r = idx % 120;
        int i = (int)((1.0f + sqrtf(1.0f + 8.0f*(float)r)) * 0.5f);
        int tri = (i*(i-1)) >> 1;
        if (r < tri) { i--; tri = (i*(i-1)) >> 1; }
        else if (r >= tri + i) { i++; tri = (i*(i-1)) >> 1; }
        int m = r - tri;
        int base = hh * 64;
        float acc = 0.f;
        #pragma unroll
        for (int d = 0; d < 64; d++) acc = fmaf(sN[m][base+d], sW[i][base+d], acc);
        g_Q2[qbase + (size_t)hh*(L*L) + m*L + i].y = acc;
    }
}

// ---------------- k3: chunked backward scan (3 syncs/round) + fused Wo GEMV ----------------
__global__ void __launch_bounds__(256) k_scan(const float* __restrict__ r_k,
                        const float* __restrict__ gn_w, const float* __restrict__ gn_b,
                        const float* __restrict__ Wo, float* __restrict__ out) {
    int blk = blockIdx.x;
    int eb = blk >> 2, h = blk & 3;
    int tid = threadIdx.x;
    int jb = h * 64;
    __shared__ float su[64], so[64];
    __shared__ float rs[L], es[L], cs[L], ss[L];
    __shared__ float osbuf[4][64];
    __shared__ float r1s[64], r2s[64], r3s[64];
    __shared__ float fin[3];
    __shared__ int sOld;
    if (tid < 64) { su[tid] = g_rlast[eb*H + jb + tid]; so[tid] = 0.f; }
    __syncthreads();
    int i16 = tid >> 4;
    int jg  = tid & 15;
    float4 wv, bvv;
    {
        size_t cb0 = ((size_t)eb*NC + (NC-1))*L*H + jb;
        wv  = *((const float4*)(g_W  + cb0 + (size_t)i16*H) + jg);
        bvv = *((const float4*)(g_Bv + cb0 + (size_t)i16*H) + jg);
    }
    #pragma unroll 1
    for (int p = NC - 1; p >= 0; --p) {
        size_t cb = ((size_t)eb*NC + p)*L*H + jb;
        float2 nv[16];
        float Ereg = 0.f;
        if (tid < 64) {
            #pragma unroll
            for (int m = 0; m < L; m++) nv[m] = g_NV[cb + (size_t)m*H + tid];
            Ereg = g_Ep[((size_t)eb*NC + p)*H + jb + tid];
        }
        float2 qcol[L];
        if (tid < 16) {
            size_t qb = (((size_t)eb*NC + p)*NH + h)*(L*L);
            #pragma unroll
            for (int m = 0; m < L; m++) qcol[m] = g_Q2[qb + m*L + tid];
        }
        float u0 = su[jg*4], u1 = su[jg*4+1], u2 = su[jg*4+2], u3 = su[jg*4+3];
        float pr = u0*wv.x + u1*wv.y + u2*wv.z + u3*wv.w;
        float pe = u0*bvv.x + u1*bvv.y + u2*bvv.z + u3*bvv.w;
        if (p > 0) {
            size_t cbn = ((size_t)eb*NC + (p-1))*L*H + jb;
            wv  = *((const float4*)(g_W  + cbn + (size_t)i16*H) + jg);
            bvv = *((const float4*)(g_Bv + cbn + (size_t)i16*H) + jg);
        }
        #pragma unroll
        for (int off = 8; off; off >>= 1) {
            pr += __shfl_xor_sync(0xffffffffu, pr, off);
            pe += __shfl_xor_sync(0xffffffffu, pe, off);
        }
        if (jg == 0) { rs[i16] = pr; es[i16] = pe; }
        __syncthreads();
        if (tid < 16) {
            float c = rs[tid], s = es[tid];
            #pragma unroll
            for (int m = 0; m < L-1; m++) {
                float sm = __shfl_sync(0x0000ffffu, s, m, 16);
                if (tid > m) {
                    c = fmaf(-sm, qcol[m].x, c);
                    s = fmaf(-sm, qcol[m].y, s);
                }
            }
            cs[tid] = c; ss[tid] = s;
        }
        __syncthreads();
        if (tid < 64) {
            float accO = 0.f, accU = 0.f;
            #pragma unroll
            for (int m = 0; m < L; m++) {
                accO = fmaf(cs[m], nv[m].y, accO);
                accU = fmaf(ss[m], nv[m].x, accU);
            }
            so[tid] += accO;
            su[tid] = Ereg * (su[tid] - accU);
        }
        __syncthreads();
    }
    if (tid < 64) {
        float o = so[tid];
        r1s[tid] = o;
        r2s[tid] = o*o;
        size_t lw = (((size_t)eb*NC + (NC-1))*L + 0)*H + jb + tid;
        r3s[tid] = g_rlast[eb*H + jb + tid] * g_W[lw] * r_k[jb + tid];
    }
    __syncthreads();
    if (tid < 32) {
        r1s[tid] += r1s[tid + 32];
        r2s[tid] += r2s[tid + 32];
        r3s[tid] += r3s[tid + 32];
        float a = wsum(r1s[tid]);
        float b2 = wsum(r2s[tid]);
        float c = wsum(r3s[tid]);
        if (tid == 0) { fin[0] = a; fin[1] = b2; fin[2] = c; }
    }
    __syncthreads();
    if (tid < 64) {
        float mean = fin[0] * (1.f/64.f);
        float var  = fin[1] * (1.f/64.f) - mean*mean;
        float inv  = rsqrtf(var + EPSc);
        float on = fmaf((so[tid] - mean)*inv, gn_w[jb + tid], gn_b[jb + tid]);
        size_t lv = (((size_t)eb*NC + (NC-1))*L + 0)*H + jb + tid;
        on = fmaf(fin[2], g_NV[lv].y, on);
        g_o[eb*H + jb + tid] = on * g_glast[eb*H + jb + tid];
    }
    __threadfence();
    if (tid == 0) sOld = atomicAdd(&g_cnt[eb], 1);
    __syncthreads();
    if (sOld == 3) {
        __threadfence();
        float* os = &osbuf[0][0];
        os[tid] = g_o[eb*H + tid];
        __syncthreads();
        float acc = 0.f;
        const float4* __restrict__ Wrow = (const float4*)(Wo + tid*H);
        #pragma unroll 16
        for (int k4 = 0; k4 < 64; k4++) {
            float4 w4 = Wrow[k4];
            acc += os[4*k4]*w4.x + os[4*k4+1]*w4.y + os[4*k4+2]*w4.z + os[4*k4+3]*w4.w;
        }
        out[eb*H + tid] = acc;
    }
}

// ---------------- launch ----------------
extern "C" void kernel_launch(void* const* d_in, const int* in_sizes, int n_in,
                              void* d_out, int out_size) {
    const float* query   = (const float*)d_in[0];
    const float* keyval  = (const float*)d_in[1];
    const float* v_first = (const float*)d_in[2];
    const float* x_r = (const float*)d_in[3];
    const float* x_w = (const float*)d_in[4];
    const float* x_k = (const float*)d_in[5];
    const float* x_v = (const float*)d_in[6];
    const float* x_a = (const float*)d_in[7];
    const float* x_g = (const float*)d_in[8];
    const float* w0  = (const float*)d_in[9];
    const float* w1  = (const float*)d_in[10];
    const float* w2  = (const float*)d_in[11];
    const float* a0  = (const float*)d_in[12];
    const float* a1  = (const float*)d_in[13];
    const float* a2  = (const float*)d_in[14];
    const float* v0  = (const float*)d_in[15];
    const float* v1  = (const float*)d_in[16];
    const float* v2  = (const float*)d_in[17];
    const float* g1  = (const float*)d_in[18];
    const float* g2  = (const float*)d_in[19];
    const float* k_k = (const float*)d_in[20];
    const float* k_a = (const float*)d_in[21];
    const float* r_k = (const float*)d_in[22];
    const float* Wr  = (const float*)d_in[23];
    const float* Wk  = (const float*)d_in[24];
    const float* Wv  = (const float*)d_in[25];
    const float* Wo  = (const float*)d_in[26];
    const float* gn_w = (const float*)d_in[27];
    const float* gn_b = (const float*)d_in[28];
    float* out = (float*)d_out;

    k_prep<<<NGB + NBTB + EB, 256>>>(keyval, query, x_k, x_v, x_w, x_a, x_r, x_g,
                                     w1, v1, a1, v2, a2, v0, g1, g2, Wr, Wk, Wv);
    k_chunk<<<dim3(NC, EB), 256>>>(v_first, w2, w0, a0, k_a, k_k);
    k_scan<<<EB*NH, 256>>>(r_k, gn_w, gn_b, Wo, out);
    (void)in_sizes; (void)n_in; (void)out_size;
}